// round 7
// baseline (speedup 1.0000x reference)
#include <cuda_runtime.h>
#include <cuda_bf16.h>

#define HH 512
#define WW 512
#define CC 64
#define CHUNK 64
#define NCHUNK (WW / CHUNK)   // 8 chunks per line
#define HALO 8                // 0.05^9 ~ 2e-12 relative truncation error

// Closed form of the 32-step relu scan (|w| <= 0.05):
//   S[j] = relu(w * x[j-1]) + max(w,0) * S[j-1];  out[j] = x[j] + S[j]
// Chunked with HALO warm-up. float4-vectorized: 1 thread = 4 channels.
//
// Thread map: c4 = tid&15, chunk = (tid>>4)&7, line = (tid>>7)&511, dir = tid>>16.
__global__ void __launch_bounds__(256) spatial_rnn_kernel(
    const float* __restrict__ x,
    const float* __restrict__ kr,
    const float* __restrict__ kl,
    const float* __restrict__ kd,
    const float* __restrict__ ku,
    float* __restrict__ out)
{
    int tid   = blockIdx.x * 256 + threadIdx.x;
    int c4    = tid & 15;            // which float4 within the 64 channels
    int chunk = (tid >> 4) & (NCHUNK - 1);
    int line  = (tid >> 7) & (HH - 1);
    int dir   = tid >> 16;

    const int c = c4 * 4;

    // strides in float4 units: x pixel = 16 float4, out pixel = 64 float4
    const float4* xp;
    float4* op;
    int sx, so;
    float4 w;

    const float4* x4 = (const float4*)x;
    float4* o4 = (float4*)out;

    if (dir == 0) {            // right: line = row h, out ch [0,64)
        w = make_float4(kr[c], kr[c+1], kr[c+2], kr[c+3]);
        xp = x4 + (size_t)line * (WW * 16) + c4;
        op = o4 + (size_t)line * (WW * 64) + c4;
        sx = 16;  so = 64;
    } else if (dir == 1) {     // left: scan pos 0 at j = W-1, out ch [64,128)
        w = make_float4(kl[2*CC+c], kl[2*CC+c+1], kl[2*CC+c+2], kl[2*CC+c+3]);
        xp = x4 + (size_t)line * (WW * 16) + (WW - 1) * 16 + c4;
        op = o4 + (size_t)line * (WW * 64) + (WW - 1) * 64 + 16 + c4;
        sx = -16; so = -64;
    } else if (dir == 2) {     // down: line = column w, out ch [128,192)
        w = make_float4(kd[c], kd[c+1], kd[c+2], kd[c+3]);
        xp = x4 + (size_t)line * 16 + c4;
        op = o4 + (size_t)line * 64 + 32 + c4;
        sx = WW * 16;  so = WW * 64;
    } else {                   // up: scan pos 0 at i = H-1, out ch [192,256)
        w = make_float4(ku[2*CC+c], ku[2*CC+c+1], ku[2*CC+c+2], ku[2*CC+c+3]);
        xp = x4 + (size_t)(HH - 1) * (WW * 16) + (size_t)line * 16 + c4;
        op = o4 + (size_t)(HH - 1) * (WW * 64) + (size_t)line * 64 + 48 + c4;
        sx = -(WW * 16);  so = -(WW * 64);
    }

    const float4 wp = make_float4(fmaxf(w.x, 0.f), fmaxf(w.y, 0.f),
                                  fmaxf(w.z, 0.f), fmaxf(w.w, 0.f));

    const int t0   = chunk * CHUNK;
    const int halo = (chunk == 0) ? 0 : HALO;

    xp += (long)(t0 - halo) * sx;
    op += (long)t0 * so;

    float4 S    = make_float4(0.f, 0.f, 0.f, 0.f);
    float4 prev = make_float4(0.f, 0.f, 0.f, 0.f);

    // warm-up: rebuild S from HALO steps of history, no stores
    #pragma unroll
    for (int i = 0; i < HALO; ++i) {
        if (i < halo) {
            float4 xv = __ldg(xp);
            S.x = fmaf(wp.x, S.x, fmaxf(w.x * prev.x, 0.f));
            S.y = fmaf(wp.y, S.y, fmaxf(w.y * prev.y, 0.f));
            S.z = fmaf(wp.z, S.z, fmaxf(w.z * prev.z, 0.f));
            S.w = fmaf(wp.w, S.w, fmaxf(w.w * prev.w, 0.f));
            prev = xv;
            xp += sx;
        }
    }

    // main: CHUNK steps with vectorized stores
    #pragma unroll 4
    for (int t = 0; t < CHUNK; ++t) {
        float4 xv = __ldg(xp);
        S.x = fmaf(wp.x, S.x, fmaxf(w.x * prev.x, 0.f));
        S.y = fmaf(wp.y, S.y, fmaxf(w.y * prev.y, 0.f));
        S.z = fmaf(wp.z, S.z, fmaxf(w.z * prev.z, 0.f));
        S.w = fmaf(wp.w, S.w, fmaxf(w.w * prev.w, 0.f));
        float4 ov = make_float4(xv.x + S.x, xv.y + S.y, xv.z + S.z, xv.w + S.w);
        __stcs(op, ov);
        prev = xv;
        xp += sx;
        op += so;
    }
}

extern "C" void kernel_launch(void* const* d_in, const int* in_sizes, int n_in,
                              void* d_out, int out_size) {
    const float* x  = (const float*)d_in[0];
    const float* kr = (const float*)d_in[1];
    const float* kl = (const float*)d_in[2];
    const float* kd = (const float*)d_in[3];
    const float* ku = (const float*)d_in[4];
    float* o = (float*)d_out;

    // 4 dirs * 512 lines * 8 chunks * 16 float4-threads = 262,144 threads
    spatial_rnn_kernel<<<1024, 256>>>(x, kr, kl, kd, ku, o);
}

// round 8
// speedup vs baseline: 1.0541x; 1.0541x over previous
#include <cuda_runtime.h>
#include <cuda_bf16.h>

#define HH 512
#define WW 512
#define CC 64
#define CHUNK 32
#define NCHUNK (WW / CHUNK)   // 16 chunks per line
#define HALO 8                // 0.05^9 ~ 2e-12 relative truncation error

// Closed form of the 32-step relu scan (|w| <= 0.05):
//   S[j] = relu(w * x[j-1]) + max(w,0) * S[j-1];  out[j] = x[j] + S[j]
// Chunked with HALO warm-up; float4 vectorized (1 thread = 4 channels);
// explicit 4-deep load batches to force MLP=4 per thread.
//
// Thread map: c4 = tid&15, chunk = (tid>>4)&15, line = (tid>>8)&511, dir = tid>>17.
__device__ __forceinline__ void rnn_step(float4& S, float4& prev,
                                         const float4 w, const float4 wp,
                                         const float4 xv) {
    S.x = fmaf(wp.x, S.x, fmaxf(w.x * prev.x, 0.f));
    S.y = fmaf(wp.y, S.y, fmaxf(w.y * prev.y, 0.f));
    S.z = fmaf(wp.z, S.z, fmaxf(w.z * prev.z, 0.f));
    S.w = fmaf(wp.w, S.w, fmaxf(w.w * prev.w, 0.f));
    prev = xv;
}

__global__ void __launch_bounds__(256) spatial_rnn_kernel(
    const float* __restrict__ x,
    const float* __restrict__ kr,
    const float* __restrict__ kl,
    const float* __restrict__ kd,
    const float* __restrict__ ku,
    float* __restrict__ out)
{
    int tid   = blockIdx.x * 256 + threadIdx.x;
    int c4    = tid & 15;                 // float4 index within 64 channels
    int chunk = (tid >> 4) & (NCHUNK - 1);
    int line  = (tid >> 8) & (HH - 1);
    int dir   = tid >> 17;

    const int c = c4 * 4;

    const float4* x4 = (const float4*)x;  // x pixel = 16 float4
    float4* o4 = (float4*)out;            // out pixel = 64 float4

    const float4* xp;
    float4* op;
    int sx, so;
    float4 w;

    if (dir == 0) {            // right: line = row h, out ch [0,64)
        w = make_float4(kr[c], kr[c+1], kr[c+2], kr[c+3]);
        xp = x4 + (size_t)line * (WW * 16) + c4;
        op = o4 + (size_t)line * (WW * 64) + c4;
        sx = 16;  so = 64;
    } else if (dir == 1) {     // left: scan pos 0 at j = W-1, out ch [64,128)
        w = make_float4(kl[2*CC+c], kl[2*CC+c+1], kl[2*CC+c+2], kl[2*CC+c+3]);
        xp = x4 + (size_t)line * (WW * 16) + (WW - 1) * 16 + c4;
        op = o4 + (size_t)line * (WW * 64) + (WW - 1) * 64 + 16 + c4;
        sx = -16; so = -64;
    } else if (dir == 2) {     // down: line = column w, out ch [128,192)
        w = make_float4(kd[c], kd[c+1], kd[c+2], kd[c+3]);
        xp = x4 + (size_t)line * 16 + c4;
        op = o4 + (size_t)line * 64 + 32 + c4;
        sx = WW * 16;  so = WW * 64;
    } else {                   // up: scan pos 0 at i = H-1, out ch [192,256)
        w = make_float4(ku[2*CC+c], ku[2*CC+c+1], ku[2*CC+c+2], ku[2*CC+c+3]);
        xp = x4 + (size_t)(HH - 1) * (WW * 16) + (size_t)line * 16 + c4;
        op = o4 + (size_t)(HH - 1) * (WW * 64) + (size_t)line * 64 + 48 + c4;
        sx = -(WW * 16);  so = -(WW * 64);
    }

    const float4 wp = make_float4(fmaxf(w.x, 0.f), fmaxf(w.y, 0.f),
                                  fmaxf(w.z, 0.f), fmaxf(w.w, 0.f));

    const int t0 = chunk * CHUNK;

    float4 S    = make_float4(0.f, 0.f, 0.f, 0.f);
    float4 prev = make_float4(0.f, 0.f, 0.f, 0.f);

    if (chunk != 0) {
        // warm-up: 2 batches of 4 redundant history steps, no stores
        const float4* hx = xp + (long)(t0 - HALO) * sx;
        #pragma unroll
        for (int b = 0; b < HALO / 4; ++b) {
            float4 a0 = __ldg(hx);
            float4 a1 = __ldg(hx + sx);
            float4 a2 = __ldg(hx + 2 * sx);
            float4 a3 = __ldg(hx + 3 * sx);
            hx += 4 * sx;
            rnn_step(S, prev, w, wp, a0);
            rnn_step(S, prev, w, wp, a1);
            rnn_step(S, prev, w, wp, a2);
            rnn_step(S, prev, w, wp, a3);
        }
    }

    xp += (long)t0 * sx;
    op += (long)t0 * so;

    // main: 8 batches of (4 independent loads, then 4 compute+store)
    #pragma unroll
    for (int b = 0; b < CHUNK / 4; ++b) {
        float4 a0 = __ldg(xp);
        float4 a1 = __ldg(xp + sx);
        float4 a2 = __ldg(xp + 2 * sx);
        float4 a3 = __ldg(xp + 3 * sx);
        xp += 4 * sx;

        rnn_step(S, prev, w, wp, a0);
        __stcs(op, make_float4(a0.x + S.x, a0.y + S.y, a0.z + S.z, a0.w + S.w));
        rnn_step(S, prev, w, wp, a1);
        __stcs(op + so, make_float4(a1.x + S.x, a1.y + S.y, a1.z + S.z, a1.w + S.w));
        rnn_step(S, prev, w, wp, a2);
        __stcs(op + 2 * so, make_float4(a2.x + S.x, a2.y + S.y, a2.z + S.z, a2.w + S.w));
        rnn_step(S, prev, w, wp, a3);
        __stcs(op + 3 * so, make_float4(a3.x + S.x, a3.y + S.y, a3.z + S.z, a3.w + S.w));
        op += 4 * so;
    }
}

extern "C" void kernel_launch(void* const* d_in, const int* in_sizes, int n_in,
                              void* d_out, int out_size) {
    const float* x  = (const float*)d_in[0];
    const float* kr = (const float*)d_in[1];
    const float* kl = (const float*)d_in[2];
    const float* kd = (const float*)d_in[3];
    const float* ku = (const float*)d_in[4];
    float* o = (float*)d_out;

    // 4 dirs * 512 lines * 16 chunks * 16 float4-threads = 524,288 threads
    spatial_rnn_kernel<<<2048, 256>>>(x, kr, kl, kd, ku, o);
}

// round 9
// speedup vs baseline: 1.0644x; 1.0097x over previous
#include <cuda_runtime.h>
#include <cuda_bf16.h>

#define HH 512
#define WW 512
#define CC 64
#define CHUNK 8
#define NCHUNK (WW / CHUNK)   // 64 chunks per line
#define HALO 4                // 0.05^5 ~ 3e-7 relative truncation error

// Closed form of the 32-step relu scan (|w| <= 0.05):
//   S[j] = relu(w * x[j-1]) + max(w,0) * S[j-1];  out[j] = x[j] + S[j]
// CHUNK=8 outputs per thread with HALO=4 warm-up; ALL 12 loads issued up
// front (MLP=12). float4 vectorized: 1 thread = 4 channels.
//
// Thread map: c4=tid&15, chunk=(tid>>4)&63, line=(tid>>10)&511, dir=tid>>19.
__device__ __forceinline__ void rnn_step(float4& S, float4& prev,
                                         const float4 w, const float4 wp,
                                         const float4 xv) {
    S.x = fmaf(wp.x, S.x, fmaxf(w.x * prev.x, 0.f));
    S.y = fmaf(wp.y, S.y, fmaxf(w.y * prev.y, 0.f));
    S.z = fmaf(wp.z, S.z, fmaxf(w.z * prev.z, 0.f));
    S.w = fmaf(wp.w, S.w, fmaxf(w.w * prev.w, 0.f));
    prev = xv;
}

__global__ void __launch_bounds__(256) spatial_rnn_kernel(
    const float* __restrict__ x,
    const float* __restrict__ kr,
    const float* __restrict__ kl,
    const float* __restrict__ kd,
    const float* __restrict__ ku,
    float* __restrict__ out)
{
    int tid   = blockIdx.x * 256 + threadIdx.x;
    int c4    = tid & 15;                  // float4 index within 64 channels
    int chunk = (tid >> 4) & (NCHUNK - 1);
    int line  = (tid >> 10) & (HH - 1);
    int dir   = tid >> 19;

    const int c = c4 * 4;

    const float4* x4 = (const float4*)x;   // x pixel = 16 float4
    float4* o4 = (float4*)out;             // out pixel = 64 float4

    const float4* xp;
    float4* op;
    int sx, so;
    float4 w;

    if (dir == 0) {            // right: line = row h, out ch [0,64)
        w = make_float4(kr[c], kr[c+1], kr[c+2], kr[c+3]);
        xp = x4 + (size_t)line * (WW * 16) + c4;
        op = o4 + (size_t)line * (WW * 64) + c4;
        sx = 16;  so = 64;
    } else if (dir == 1) {     // left: scan pos 0 at j = W-1, out ch [64,128)
        w = make_float4(kl[2*CC+c], kl[2*CC+c+1], kl[2*CC+c+2], kl[2*CC+c+3]);
        xp = x4 + (size_t)line * (WW * 16) + (WW - 1) * 16 + c4;
        op = o4 + (size_t)line * (WW * 64) + (WW - 1) * 64 + 16 + c4;
        sx = -16; so = -64;
    } else if (dir == 2) {     // down: line = column w, out ch [128,192)
        w = make_float4(kd[c], kd[c+1], kd[c+2], kd[c+3]);
        xp = x4 + (size_t)line * 16 + c4;
        op = o4 + (size_t)line * 64 + 32 + c4;
        sx = WW * 16;  so = WW * 64;
    } else {                   // up: scan pos 0 at i = H-1, out ch [192,256)
        w = make_float4(ku[2*CC+c], ku[2*CC+c+1], ku[2*CC+c+2], ku[2*CC+c+3]);
        xp = x4 + (size_t)(HH - 1) * (WW * 16) + (size_t)line * 16 + c4;
        op = o4 + (size_t)(HH - 1) * (WW * 64) + (size_t)line * 64 + 48 + c4;
        sx = -(WW * 16);  so = -(WW * 64);
    }

    const float4 wp = make_float4(fmaxf(w.x, 0.f), fmaxf(w.y, 0.f),
                                  fmaxf(w.z, 0.f), fmaxf(w.w, 0.f));

    const int t0   = chunk * CHUNK;
    const int halo = chunk ? HALO : 0;     // chunk 0: no history

    const float4* hx = xp + (long)(t0 - halo) * sx;  // == xp+t0*sx when chunk==0
    xp += (long)t0 * sx;
    op += (long)t0 * so;

    // ---- issue ALL loads up front: 4 halo + 8 main, independent (MLP=12) ----
    float4 h0 = __ldg(hx);
    float4 h1 = __ldg(hx + sx);
    float4 h2 = __ldg(hx + 2 * sx);
    float4 h3 = __ldg(hx + 3 * sx);
    float4 m0 = __ldg(xp);
    float4 m1 = __ldg(xp + sx);
    float4 m2 = __ldg(xp + 2 * sx);
    float4 m3 = __ldg(xp + 3 * sx);
    float4 m4 = __ldg(xp + 4 * sx);
    float4 m5 = __ldg(xp + 5 * sx);
    float4 m6 = __ldg(xp + 6 * sx);
    float4 m7 = __ldg(xp + 7 * sx);

    float4 S    = make_float4(0.f, 0.f, 0.f, 0.f);
    float4 prev = make_float4(0.f, 0.f, 0.f, 0.f);

    // warm-up (skipped for chunk 0: prev stays 0 = zero padding)
    if (chunk) {
        rnn_step(S, prev, w, wp, h0);
        rnn_step(S, prev, w, wp, h1);
        rnn_step(S, prev, w, wp, h2);
        rnn_step(S, prev, w, wp, h3);
    }

    // main: 8 compute+store steps
    rnn_step(S, prev, w, wp, m0);
    __stcs(op,          make_float4(m0.x + S.x, m0.y + S.y, m0.z + S.z, m0.w + S.w));
    rnn_step(S, prev, w, wp, m1);
    __stcs(op + so,     make_float4(m1.x + S.x, m1.y + S.y, m1.z + S.z, m1.w + S.w));
    rnn_step(S, prev, w, wp, m2);
    __stcs(op + 2 * so, make_float4(m2.x + S.x, m2.y + S.y, m2.z + S.z, m2.w + S.w));
    rnn_step(S, prev, w, wp, m3);
    __stcs(op + 3 * so, make_float4(m3.x + S.x, m3.y + S.y, m3.z + S.z, m3.w + S.w));
    rnn_step(S, prev, w, wp, m4);
    __stcs(op + 4 * so, make_float4(m4.x + S.x, m4.y + S.y, m4.z + S.z, m4.w + S.w));
    rnn_step(S, prev, w, wp, m5);
    __stcs(op + 5 * so, make_float4(m5.x + S.x, m5.y + S.y, m5.z + S.z, m5.w + S.w));
    rnn_step(S, prev, w, wp, m6);
    __stcs(op + 6 * so, make_float4(m6.x + S.x, m6.y + S.y, m6.z + S.z, m6.w + S.w));
    rnn_step(S, prev, w, wp, m7);
    __stcs(op + 7 * so, make_float4(m7.x + S.x, m7.y + S.y, m7.z + S.z, m7.w + S.w));
}

extern "C" void kernel_launch(void* const* d_in, const int* in_sizes, int n_in,
                              void* d_out, int out_size) {
    const float* x  = (const float*)d_in[0];
    const float* kr = (const float*)d_in[1];
    const float* kl = (const float*)d_in[2];
    const float* kd = (const float*)d_in[3];
    const float* ku = (const float*)d_in[4];
    float* o = (float*)d_out;

    // 4 dirs * 512 lines * 64 chunks * 16 float4-threads = 2,097,152 threads
    spatial_rnn_kernel<<<8192, 256>>>(x, kr, kl, kd, ku, o);
}

// round 11
// speedup vs baseline: 1.4803x; 1.3907x over previous
#include <cuda_runtime.h>
#include <cuda_bf16.h>

#define HH 512
#define WW 512
#define CC 64
#define CHUNK 8
#define NCHUNK (WW / CHUNK)   // 64 chunks per line
#define HALO 4                // 0.05^5 ~ 3e-7 relative truncation error

// Closed form of the 32-step relu scan (|w| <= 0.05):
//   S[j] = relu(w * x[j-1]) + max(w,0) * S[j-1];  out[j] = x[j] + S[j]
//
// Band-locality schedule: blocks are grouped into 64 "bands" of 8 rows.
// Band b's 128 blocks (64 row-dir + 64 col-dir) all read the SAME ~1.2MB of
// input (rows [8b, 8b+8)), so the 4 directional passes share one DRAM fetch
// via L2. Descending scans map scan-chunk = 63 - physical-chunk so their
// coverage aligns physically with ascending scans.
//
// Per-thread: CHUNK=8 outputs, HALO=4 warm-up, all 12 float4 loads issued
// up front (MLP=12). 1 thread = 4 channels.
__device__ __forceinline__ void rnn_step(float4& S, float4& prev,
                                         const float4 w, const float4 wp,
                                         const float4 xv) {
    S.x = fmaf(wp.x, S.x, fmaxf(w.x * prev.x, 0.f));
    S.y = fmaf(wp.y, S.y, fmaxf(w.y * prev.y, 0.f));
    S.z = fmaf(wp.z, S.z, fmaxf(w.z * prev.z, 0.f));
    S.w = fmaf(wp.w, S.w, fmaxf(w.w * prev.w, 0.f));
    prev = xv;
}

__global__ void __launch_bounds__(256) spatial_rnn_kernel(
    const float* __restrict__ x,
    const float* __restrict__ kr,
    const float* __restrict__ kl,
    const float* __restrict__ kd,
    const float* __restrict__ ku,
    float* __restrict__ out)
{
    const int band = blockIdx.x >> 7;        // 64 bands of 8 rows
    const int sub  = blockIdx.x & 127;       // 128 blocks per band
    const int g    = threadIdx.x >> 4;       // 16 thread-groups per block
    const int c4   = threadIdx.x & 15;       // float4 index within 64 channels
    const int c    = c4 * 4;

    int dir, line, schunk;                   // schunk = chunk in SCAN coords
    if (sub < 64) {
        // row dirs: this block = one physical column-chunk, 2 dirs x 8 lines
        dir  = g >> 3;                       // 0 = right, 1 = left
        line = band * 8 + (g & 7);           // row
        schunk = dir ? (63 - sub) : sub;     // align physical coverage
    } else {
        // col dirs: this block = 8 columns, 2 dirs; row-chunk = this band
        dir  = 2 + (g >> 3);                 // 2 = down, 3 = up
        line = (sub - 64) * 8 + (g & 7);     // column
        schunk = (dir == 3) ? (63 - band) : band;
    }

    const float4* x4 = (const float4*)x;     // x pixel = 16 float4
    float4* o4 = (float4*)out;               // out pixel = 64 float4

    const float4* xp;
    float4* op;
    int sx, so;
    float4 w;

    if (dir == 0) {            // right: scan W ascending, out ch [0,64)
        w = make_float4(kr[c], kr[c+1], kr[c+2], kr[c+3]);
        xp = x4 + (size_t)line * (WW * 16) + c4;
        op = o4 + (size_t)line * (WW * 64) + c4;
        sx = 16;  so = 64;
    } else if (dir == 1) {     // left: scan W descending from j=W-1, out ch [64,128)
        w = make_float4(kl[2*CC+c], kl[2*CC+c+1], kl[2*CC+c+2], kl[2*CC+c+3]);
        xp = x4 + (size_t)line * (WW * 16) + (WW - 1) * 16 + c4;
        op = o4 + (size_t)line * (WW * 64) + (WW - 1) * 64 + 16 + c4;
        sx = -16; so = -64;
    } else if (dir == 2) {     // down: scan H ascending, out ch [128,192)
        w = make_float4(kd[c], kd[c+1], kd[c+2], kd[c+3]);
        xp = x4 + (size_t)line * 16 + c4;
        op = o4 + (size_t)line * 64 + 32 + c4;
        sx = WW * 16;  so = WW * 64;
    } else {                   // up: scan H descending from i=H-1, out ch [192,256)
        w = make_float4(ku[2*CC+c], ku[2*CC+c+1], ku[2*CC+c+2], ku[2*CC+c+3]);
        xp = x4 + (size_t)(HH - 1) * (WW * 16) + (size_t)line * 16 + c4;
        op = o4 + (size_t)(HH - 1) * (WW * 64) + (size_t)line * 64 + 48 + c4;
        sx = -(WW * 16);  so = -(WW * 64);
    }

    const float4 wp = make_float4(fmaxf(w.x, 0.f), fmaxf(w.y, 0.f),
                                  fmaxf(w.z, 0.f), fmaxf(w.w, 0.f));

    const int t0   = schunk * CHUNK;
    const int halo = schunk ? HALO : 0;      // scan-chunk 0: true line start

    const float4* hx = xp + (long)(t0 - halo) * sx;
    xp += (long)t0 * sx;
    op += (long)t0 * so;

    // ---- issue ALL loads up front: 4 halo + 8 main, independent (MLP=12) ----
    float4 h0 = __ldg(hx);
    float4 h1 = __ldg(hx + sx);
    float4 h2 = __ldg(hx + 2 * sx);
    float4 h3 = __ldg(hx + 3 * sx);
    float4 m0 = __ldg(xp);
    float4 m1 = __ldg(xp + sx);
    float4 m2 = __ldg(xp + 2 * sx);
    float4 m3 = __ldg(xp + 3 * sx);
    float4 m4 = __ldg(xp + 4 * sx);
    float4 m5 = __ldg(xp + 5 * sx);
    float4 m6 = __ldg(xp + 6 * sx);
    float4 m7 = __ldg(xp + 7 * sx);

    float4 S    = make_float4(0.f, 0.f, 0.f, 0.f);
    float4 prev = make_float4(0.f, 0.f, 0.f, 0.f);

    // warm-up (skipped at true line start: prev stays 0 = zero padding)
    if (schunk) {
        rnn_step(S, prev, w, wp, h0);
        rnn_step(S, prev, w, wp, h1);
        rnn_step(S, prev, w, wp, h2);
        rnn_step(S, prev, w, wp, h3);
    }

    // main: 8 compute+store steps
    rnn_step(S, prev, w, wp, m0);
    __stcs(op,          make_float4(m0.x + S.x, m0.y + S.y, m0.z + S.z, m0.w + S.w));
    rnn_step(S, prev, w, wp, m1);
    __stcs(op + so,     make_float4(m1.x + S.x, m1.y + S.y, m1.z + S.z, m1.w + S.w));
    rnn_step(S, prev, w, wp, m2);
    __stcs(op + 2 * so, make_float4(m2.x + S.x, m2.y + S.y, m2.z + S.z, m2.w + S.w));
    rnn_step(S, prev, w, wp, m3);
    __stcs(op + 3 * so, make_float4(m3.x + S.x, m3.y + S.y, m3.z + S.z, m3.w + S.w));
    rnn_step(S, prev, w, wp, m4);
    __stcs(op + 4 * so, make_float4(m4.x + S.x, m4.y + S.y, m4.z + S.z, m4.w + S.w));
    rnn_step(S, prev, w, wp, m5);
    __stcs(op + 5 * so, make_float4(m5.x + S.x, m5.y + S.y, m5.z + S.z, m5.w + S.w));
    rnn_step(S, prev, w, wp, m6);
    __stcs(op + 6 * so, make_float4(m6.x + S.x, m6.y + S.y, m6.z + S.z, m6.w + S.w));
    rnn_step(S, prev, w, wp, m7);
    __stcs(op + 7 * so, make_float4(m7.x + S.x, m7.y + S.y, m7.z + S.z, m7.w + S.w));
}

extern "C" void kernel_launch(void* const* d_in, const int* in_sizes, int n_in,
                              void* d_out, int out_size) {
    const float* x  = (const float*)d_in[0];
    const float* kr = (const float*)d_in[1];
    const float* kl = (const float*)d_in[2];
    const float* kd = (const float*)d_in[3];
    const float* ku = (const float*)d_in[4];
    float* o = (float*)d_out;

    // 64 bands * 128 blocks = 8192 blocks, 256 threads each
    spatial_rnn_kernel<<<8192, 256>>>(x, kr, kl, kd, ku, o);
}